// round 1
// baseline (speedup 1.0000x reference)
#include <cuda_runtime.h>

// Problem constants
#define HB   4
#define HS   1024
#define HD   1024
#define HH   16
#define HDK  64
#define MTOT (HB*HS)          // 4096
#define NBH  (HB*HH)          // 64
#define OUT_ELEMS (MTOT*HD)   // 4194304 floats (then attn: 64*1024*1024)

// Scratch (allocation-free: device globals)
__device__ float g_Q[NBH*HS*HDK];
__device__ float g_K[NBH*HS*HDK];
__device__ float g_V[NBH*HS*HDK];
__device__ float g_ctx[MTOT*HD];

// ---------------------------------------------------------------------------
// GEMM: Y = X[4096,1024] @ W[1024,1024] + bias
// BM=128, BN=64, BK=16, 256 threads, 8x4 per-thread microtile.
// HEAD_OUT: scatter to head-major layout [(b*H+h)*S+s]*64+d ; else row-major.
// ---------------------------------------------------------------------------
template<bool HEAD_OUT>
__global__ __launch_bounds__(256)
void gemm_k(const float* __restrict__ X, const float* __restrict__ W,
            const float* __restrict__ bias, float* __restrict__ Y)
{
    __shared__ float As[16][128 + 4];   // k-major (transposed), stride 132
    __shared__ float Bs[16][64 + 4];    // stride 68

    const int tid = threadIdx.x;
    const int m0 = blockIdx.y * 128;
    const int n0 = blockIdx.x * 64;
    const int tm = tid >> 4;    // 0..15 -> rows tm*8..+7
    const int tn = tid & 15;    // 0..15 -> cols tn*4..+3

    float acc[8][4];
#pragma unroll
    for (int i = 0; i < 8; i++)
#pragma unroll
        for (int j = 0; j < 4; j++) acc[i][j] = 0.f;

    for (int k0 = 0; k0 < 1024; k0 += 16) {
        // Load A tile 128x16 (512 float4), transpose into As[k][m]
#pragma unroll
        for (int it = 0; it < 2; it++) {
            int lin = it * 256 + tid;       // 0..511
            int m   = lin >> 2;
            int k4  = (lin & 3) << 2;
            float4 a = *(const float4*)&X[(size_t)(m0 + m) * 1024 + k0 + k4];
            As[k4 + 0][m] = a.x;
            As[k4 + 1][m] = a.y;
            As[k4 + 2][m] = a.z;
            As[k4 + 3][m] = a.w;
        }
        // Load B tile 16x64 (256 float4)
        {
            int row = tid >> 4;
            int c4  = (tid & 15) << 2;
            *(float4*)&Bs[row][c4] =
                *(const float4*)&W[(size_t)(k0 + row) * 1024 + n0 + c4];
        }
        __syncthreads();

#pragma unroll
        for (int k = 0; k < 16; k++) {
            float4 a0 = *(const float4*)&As[k][tm * 8];
            float4 a1 = *(const float4*)&As[k][tm * 8 + 4];
            float4 b0 = *(const float4*)&Bs[k][tn * 4];
            float a[8] = {a0.x, a0.y, a0.z, a0.w, a1.x, a1.y, a1.z, a1.w};
            float b[4] = {b0.x, b0.y, b0.z, b0.w};
#pragma unroll
            for (int i = 0; i < 8; i++)
#pragma unroll
                for (int j = 0; j < 4; j++) acc[i][j] += a[i] * b[j];
        }
        __syncthreads();
    }

    // Epilogue (+bias), float4 stores
    const int n = n0 + tn * 4;
    float4 bv = *(const float4*)&bias[n];
#pragma unroll
    for (int i = 0; i < 8; i++) {
        int m = m0 + tm * 8 + i;
        float4 v = make_float4(acc[i][0] + bv.x, acc[i][1] + bv.y,
                               acc[i][2] + bv.z, acc[i][3] + bv.w);
        if (HEAD_OUT) {
            int b = m >> 10, s = m & 1023;
            int h = n >> 6,  d = n & 63;
            *(float4*)&Y[(((size_t)(b * HH + h)) * HS + s) * HDK + d] = v;
        } else {
            *(float4*)&Y[(size_t)m * HD + n] = v;
        }
    }
}

// ---------------------------------------------------------------------------
// Fused attention: per block = one (b,h) x 32 query rows.
// Phase 1: S = (Q*0.125) @ K^T   (full 32x1024 row block in smem)
// Phase 2: row softmax (8 lanes/row, shuffle reduce), write attn to gmem
// Phase 3: ctx = P @ V -> g_ctx (row-major [b*S+s][h*64+d])
// ---------------------------------------------------------------------------
#define SSTR 1032                 // 1024 + 8 (bank stagger)
#define QSTR 36
#define KSTR 132
#define VSTR 68
#define SM_FLOATS (32*SSTR + 64*QSTR + 128*VSTR)   // 33024+2304+8704 = 44032
#define SM_BYTES  (SM_FLOATS * 4)                   // 176128

__global__ __launch_bounds__(256)
void attn_k(float* __restrict__ attn_out)
{
    extern __shared__ float sm[];
    float* Ss  = sm;                          // [32][SSTR]
    float* QsT = sm + 32 * SSTR;              // [64][QSTR] (d-major)
    float* KsT = sm + 32 * SSTR + 64 * QSTR;  // [64][KSTR] / reused as Vs[128][VSTR]

    const int tid = threadIdx.x;
    const int bh  = blockIdx.y;
    const int q0  = blockIdx.x * 32;
    const float* Qg = g_Q + (size_t)bh * HS * HDK;
    const float* Kg = g_K + (size_t)bh * HS * HDK;
    const float* Vg = g_V + (size_t)bh * HS * HDK;

    // ---- load Q tile (32x64) transposed + pre-scaled by 1/sqrt(64) ----
#pragma unroll
    for (int it = 0; it < 8; it++) {
        int lin = it * 256 + tid;        // 0..2047
        int row = lin >> 6;
        int d   = lin & 63;
        QsT[d * QSTR + row] = Qg[(size_t)(q0 + row) * 64 + d] * 0.125f;
    }
    __syncthreads();

    // ---- Phase 1: scores ----
    const int ty = tid >> 5;   // 0..7  -> q rows ty*4..+3
    const int tx = tid & 31;   // keys tx*4..+3 within 128-key tile
    for (int kt = 0; kt < 8; kt++) {
        // load K tile [128 keys][64 d] transposed into KsT[d][j]
#pragma unroll
        for (int it = 0; it < 8; it++) {
            int lin = it * 256 + tid;                  // float4 granules, 0..2047
            int j   = (lin & 7) + ((lin >> 7) << 3);   // 0..127
            int d4  = ((lin >> 3) & 15) << 2;          // 0..60
            float4 kv = *(const float4*)&Kg[(size_t)(kt * 128 + j) * 64 + d4];
            KsT[(d4 + 0) * KSTR + j] = kv.x;
            KsT[(d4 + 1) * KSTR + j] = kv.y;
            KsT[(d4 + 2) * KSTR + j] = kv.z;
            KsT[(d4 + 3) * KSTR + j] = kv.w;
        }
        __syncthreads();

        float acc[4][4];
#pragma unroll
        for (int i = 0; i < 4; i++)
#pragma unroll
            for (int j = 0; j < 4; j++) acc[i][j] = 0.f;

#pragma unroll 8
        for (int d = 0; d < 64; d++) {
            float4 qa = *(const float4*)&QsT[d * QSTR + ty * 4];  // broadcast
            float4 kb = *(const float4*)&KsT[d * KSTR + tx * 4];  // coalesced
            float a[4] = {qa.x, qa.y, qa.z, qa.w};
            float b[4] = {kb.x, kb.y, kb.z, kb.w};
#pragma unroll
            for (int i = 0; i < 4; i++)
#pragma unroll
                for (int j = 0; j < 4; j++) acc[i][j] += a[i] * b[j];
        }
#pragma unroll
        for (int i = 0; i < 4; i++) {
            float4 v = make_float4(acc[i][0], acc[i][1], acc[i][2], acc[i][3]);
            *(float4*)&Ss[(size_t)(ty * 4 + i) * SSTR + kt * 128 + tx * 4] = v;
        }
        __syncthreads();
    }

    // ---- Phase 2: softmax (8 threads per row) ----
    {
        const int row = tid >> 3;
        const int t8  = tid & 7;
        float* srow = Ss + (size_t)row * SSTR;

        float mx = -1e30f;
#pragma unroll
        for (int i = 0; i < 32; i++) {
            float4 v = *(const float4*)&srow[t8 * 4 + i * 32];
            mx = fmaxf(mx, fmaxf(fmaxf(v.x, v.y), fmaxf(v.z, v.w)));
        }
#pragma unroll
        for (int o = 4; o >= 1; o >>= 1)
            mx = fmaxf(mx, __shfl_xor_sync(0xffffffffu, mx, o));

        float sum = 0.f;
#pragma unroll
        for (int i = 0; i < 32; i++) {
            float4 v = *(float4*)&srow[t8 * 4 + i * 32];
            v.x = __expf(v.x - mx); v.y = __expf(v.y - mx);
            v.z = __expf(v.z - mx); v.w = __expf(v.w - mx);
            sum += v.x + v.y + v.z + v.w;
            *(float4*)&srow[t8 * 4 + i * 32] = v;
        }
#pragma unroll
        for (int o = 4; o >= 1; o >>= 1)
            sum += __shfl_xor_sync(0xffffffffu, sum, o);
        float inv = 1.f / sum;

        float* arow = attn_out + ((size_t)bh * HS + q0 + row) * HS;
#pragma unroll
        for (int i = 0; i < 32; i++) {
            float4 v = *(float4*)&srow[t8 * 4 + i * 32];
            v.x *= inv; v.y *= inv; v.z *= inv; v.w *= inv;
            *(float4*)&srow[t8 * 4 + i * 32] = v;
            *(float4*)&arow[t8 * 4 + i * 32] = v;
        }
    }
    __syncthreads();

    // ---- Phase 3: ctx = P @ V ----
    {
        float* Vs = KsT;                 // reuse buffer: [128][VSTR]
        const int rg  = tid >> 5;        // warp id -> rows rg*4..+3
        const int txl = tid & 31;        // d pair txl*2
        float c[4][2];
#pragma unroll
        for (int i = 0; i < 4; i++) { c[i][0] = 0.f; c[i][1] = 0.f; }

        for (int kt = 0; kt < 8; kt++) {
#pragma unroll
            for (int it = 0; it < 8; it++) {
                int lin = it * 256 + tid;        // float4 granules
                int j   = lin >> 4;              // 0..127
                int d4  = (lin & 15) << 2;
                float4 vv = *(const float4*)&Vg[(size_t)(kt * 128 + j) * 64 + d4];
                *(float4*)&Vs[j * VSTR + d4] = vv;
            }
            __syncthreads();

#pragma unroll 4
            for (int j = 0; j < 128; j++) {
                int jg = kt * 128 + j;
                float2 vv = *(const float2*)&Vs[j * VSTR + txl * 2];
#pragma unroll
                for (int i = 0; i < 4; i++) {
                    float p = Ss[(size_t)(rg * 4 + i) * SSTR + jg];   // broadcast
                    c[i][0] += p * vv.x;
                    c[i][1] += p * vv.y;
                }
            }
            __syncthreads();
        }

        const int b = bh >> 4, h = bh & 15;
#pragma unroll
        for (int i = 0; i < 4; i++) {
            int s = q0 + rg * 4 + i;
            *(float2*)&g_ctx[((size_t)(b * HS + s)) * HD + h * 64 + txl * 2] =
                make_float2(c[i][0], c[i][1]);
        }
    }
}

// ---------------------------------------------------------------------------
extern "C" void kernel_launch(void* const* d_in, const int* in_sizes, int n_in,
                              void* d_out, int out_size)
{
    const float* q  = (const float*)d_in[0];
    const float* k  = (const float*)d_in[1];
    const float* v  = (const float*)d_in[2];
    const float* Wq = (const float*)d_in[3];
    const float* bq = (const float*)d_in[4];
    const float* Wk = (const float*)d_in[5];
    const float* bk = (const float*)d_in[6];
    const float* Wv = (const float*)d_in[7];
    const float* bv = (const float*)d_in[8];
    const float* Wo = (const float*)d_in[9];
    const float* bo = (const float*)d_in[10];

    float* out  = (float*)d_out;
    float* attn = out + OUT_ELEMS;

    float *gQ, *gK, *gV, *gctx;
    cudaGetSymbolAddress((void**)&gQ,   g_Q);
    cudaGetSymbolAddress((void**)&gK,   g_K);
    cudaGetSymbolAddress((void**)&gV,   g_V);
    cudaGetSymbolAddress((void**)&gctx, g_ctx);

    cudaFuncSetAttribute(attn_k, cudaFuncAttributeMaxDynamicSharedMemorySize,
                         SM_BYTES);

    dim3 gg(HD / 64, MTOT / 128);   // (16, 32)
    gemm_k<true><<<gg, 256>>>(q, Wq, bq, gQ);
    gemm_k<true><<<gg, 256>>>(k, Wk, bk, gK);
    gemm_k<true><<<gg, 256>>>(v, Wv, bv, gV);

    attn_k<<<dim3(HS / 32, NBH), 256, SM_BYTES>>>(attn);

    gemm_k<false><<<gg, 256>>>(gctx, Wo, bo, out);
}

// round 3
// speedup vs baseline: 2.1219x; 2.1219x over previous
#include <cuda_runtime.h>
#include <cuda_bf16.h>
#include <cstdint>

// Problem constants
#define HB   4
#define HS   1024
#define HD   1024
#define HH   16
#define HDK  64
#define MTOT (HB*HS)          // 4096
#define NBH  (HB*HH)          // 64
#define OUT_ELEMS (MTOT*HD)   // 4194304

// Scratch (allocation-free: device globals)
__device__ __nv_bfloat16 g_Xhi[MTOT*HD];
__device__ __nv_bfloat16 g_Xlo[MTOT*HD];
__device__ __nv_bfloat16 g_Whi[HD*HD];     // W^T [n][k]
__device__ __nv_bfloat16 g_Wlo[HD*HD];
__device__ __nv_bfloat16 g_Qhi[NBH*HS*HDK];  // [bh][s][d], pre-scaled
__device__ __nv_bfloat16 g_Qlo[NBH*HS*HDK];
__device__ __nv_bfloat16 g_Khi[NBH*HS*HDK];
__device__ __nv_bfloat16 g_Klo[NBH*HS*HDK];
__device__ float         g_Vf [NBH*HS*HDK];  // [bh][s][d] fp32
__device__ __nv_bfloat16 g_VThi[NBH*HDK*HS]; // [bh][d][s]
__device__ __nv_bfloat16 g_VTlo[NBH*HDK*HS];

// ---------------------------------------------------------------------------
// helpers
// ---------------------------------------------------------------------------
__device__ __forceinline__ uint32_t smem_u32(const void* p) {
    uint32_t a;
    asm("{ .reg .u64 t; cvta.to.shared.u64 t, %1; cvt.u32.u64 %0, t; }"
        : "=r"(a) : "l"(p));
    return a;
}
__device__ __forceinline__ void ldmx4(uint32_t* r, uint32_t addr) {
    asm volatile("ldmatrix.sync.aligned.m8n8.x4.shared.b16 {%0,%1,%2,%3}, [%4];"
        : "=r"(r[0]), "=r"(r[1]), "=r"(r[2]), "=r"(r[3]) : "r"(addr));
}
__device__ __forceinline__ void mma_bf16(float* c, const uint32_t* a,
                                         uint32_t b0, uint32_t b1) {
    asm volatile(
        "mma.sync.aligned.m16n8k16.row.col.f32.bf16.bf16.f32 "
        "{%0,%1,%2,%3}, {%4,%5,%6,%7}, {%8,%9}, {%0,%1,%2,%3};"
        : "+f"(c[0]), "+f"(c[1]), "+f"(c[2]), "+f"(c[3])
        : "r"(a[0]), "r"(a[1]), "r"(a[2]), "r"(a[3]), "r"(b0), "r"(b1));
}
__device__ __forceinline__ void split2(float x, float y,
                                       uint32_t& hi, uint32_t& lo) {
    __nv_bfloat16 hx = __float2bfloat16(x), hy = __float2bfloat16(y);
    __nv_bfloat16 lx = __float2bfloat16(x - __bfloat162float(hx));
    __nv_bfloat16 ly = __float2bfloat16(y - __bfloat162float(hy));
    __nv_bfloat162 h2(hx, hy), l2(lx, ly);
    hi = *(uint32_t*)&h2;
    lo = *(uint32_t*)&l2;
}

// ---------------------------------------------------------------------------
// fp32 -> (hi, lo) bf16 split, elementwise (for GEMM input X)
// ---------------------------------------------------------------------------
__global__ __launch_bounds__(256)
void split_k(const float4* __restrict__ x, uint32_t* __restrict__ hi,
             uint32_t* __restrict__ lo, int n4)
{
    int i = blockIdx.x * 256 + threadIdx.x;
    if (i >= n4) return;
    float4 v = x[i];
    uint32_t h0, l0, h1, l1;
    split2(v.x, v.y, h0, l0);
    split2(v.z, v.w, h1, l1);
    hi[2*i] = h0; hi[2*i+1] = h1;
    lo[2*i] = l0; lo[2*i+1] = l1;
}

// ---------------------------------------------------------------------------
// W[k][n] fp32 -> W^T hi/lo [n][k] bf16
// ---------------------------------------------------------------------------
__global__ __launch_bounds__(256)
void wT_split_k(const float* __restrict__ W, __nv_bfloat16* __restrict__ hiT,
                __nv_bfloat16* __restrict__ loT)
{
    __shared__ float t[32][33];
    int k0 = blockIdx.y * 32, n0 = blockIdx.x * 32;
    int tx = threadIdx.x, ty = threadIdx.y;   // (32, 8)
#pragma unroll
    for (int j = 0; j < 32; j += 8)
        t[ty + j][tx] = W[(size_t)(k0 + ty + j) * HD + n0 + tx];
    __syncthreads();
#pragma unroll
    for (int j = 0; j < 32; j += 8) {
        float v = t[tx][ty + j];
        __nv_bfloat16 h = __float2bfloat16(v);
        __nv_bfloat16 l = __float2bfloat16(v - __bfloat162float(h));
        size_t o = (size_t)(n0 + ty + j) * HD + k0 + tx;
        hiT[o] = h;
        loT[o] = l;
    }
}

// ---------------------------------------------------------------------------
// g_Vf [bh][s][d] -> g_VThi/lo [bh][d][s]
// ---------------------------------------------------------------------------
__global__ __launch_bounds__(256)
void vT_split_k()
{
    __shared__ float t[32][33];
    int bh = blockIdx.y;
    int s0 = (blockIdx.x & 31) * 32;
    int d0 = (blockIdx.x >> 5) * 32;
    int tx = threadIdx.x, ty = threadIdx.y;   // (32, 8)
    const float* V = g_Vf + (size_t)bh * HS * HDK;
#pragma unroll
    for (int j = 0; j < 32; j += 8)
        t[ty + j][tx] = V[(size_t)(s0 + ty + j) * HDK + d0 + tx];
    __syncthreads();
    __nv_bfloat16* Hi = g_VThi + (size_t)bh * HDK * HS;
    __nv_bfloat16* Lo = g_VTlo + (size_t)bh * HDK * HS;
#pragma unroll
    for (int j = 0; j < 32; j += 8) {
        float v = t[tx][ty + j];
        __nv_bfloat16 h = __float2bfloat16(v);
        __nv_bfloat16 l = __float2bfloat16(v - __bfloat162float(h));
        size_t o = (size_t)(d0 + ty + j) * HS + s0 + tx;
        Hi[o] = h;
        Lo[o] = l;
    }
}

// ---------------------------------------------------------------------------
// warp-MMA GEMM: Y[4096,1024] = X @ W + bias (split-bf16, 3 MMAs/product)
// BM=128, BN=128, BK=32. 8 warps: wm=wid&3 (32 rows), wn=wid>>2 (64 cols).
// MODE: 0 = fp32 row-major (final out), 1 = bf16 split head-major *0.125 (Q),
//       2 = bf16 split head-major (K), 3 = fp32 head-major (V)
// ---------------------------------------------------------------------------
#define GSTR 80                     // smem bytes per 32-bf16 row (64B + 16 pad)
#define GMAT (128*GSTR)             // 10240 per matrix
#define GSTAGE (4*GMAT)             // Ahi, Alo, Bhi, Blo
#define GT_SMEM (2*GSTAGE)          // 81920

template<int MODE>
__global__ __launch_bounds__(256, 1)
void gemm_mma(const __nv_bfloat16* __restrict__ Xhi, const __nv_bfloat16* __restrict__ Xlo,
              const float* __restrict__ bias,
              float* __restrict__ Yf,
              __nv_bfloat16* __restrict__ Yhi, __nv_bfloat16* __restrict__ Ylo)
{
    extern __shared__ char sm[];
    const uint32_t sb = smem_u32(sm);
    const int tid = threadIdx.x;
    const int wid = tid >> 5, lane = tid & 31;
    const int wm = wid & 3, wn = wid >> 2;
    const int m0 = blockIdx.y * 128, n0 = blockIdx.x * 128;

    const __nv_bfloat16* Whi = g_Whi;
    const __nv_bfloat16* Wlo = g_Wlo;

    float acc[16][4];
#pragma unroll
    for (int i = 0; i < 16; i++)
#pragma unroll
        for (int j = 0; j < 4; j++) acc[i][j] = 0.f;

    // granule coords for loads (2 granules/thread/matrix)
    const int r0g = tid >> 2,          c0g = tid & 3;
    const int r1g = (tid + 256) >> 2,  c1g = tid & 3;

    auto load_regs = [&](int k0, uint4* b) {
        const __nv_bfloat16* pa0 = Xhi + (size_t)(m0 + r0g) * HD + k0;
        const __nv_bfloat16* pa1 = Xhi + (size_t)(m0 + r1g) * HD + k0;
        const __nv_bfloat16* pl0 = Xlo + (size_t)(m0 + r0g) * HD + k0;
        const __nv_bfloat16* pl1 = Xlo + (size_t)(m0 + r1g) * HD + k0;
        const __nv_bfloat16* pb0 = Whi + (size_t)(n0 + r0g) * HD + k0;
        const __nv_bfloat16* pb1 = Whi + (size_t)(n0 + r1g) * HD + k0;
        const __nv_bfloat16* pc0 = Wlo + (size_t)(n0 + r0g) * HD + k0;
        const __nv_bfloat16* pc1 = Wlo + (size_t)(n0 + r1g) * HD + k0;
        b[0] = ((const uint4*)pa0)[c0g];
        b[1] = ((const uint4*)pa1)[c1g];
        b[2] = ((const uint4*)pl0)[c0g];
        b[3] = ((const uint4*)pl1)[c1g];
        b[4] = ((const uint4*)pb0)[c0g];
        b[5] = ((const uint4*)pb1)[c1g];
        b[6] = ((const uint4*)pc0)[c0g];
        b[7] = ((const uint4*)pc1)[c1g];
    };
    auto store_regs = [&](int st, const uint4* b) {
        char* base = sm + st * GSTAGE;
        *(uint4*)(base + 0*GMAT + r0g*GSTR + c0g*16) = b[0];
        *(uint4*)(base + 0*GMAT + r1g*GSTR + c1g*16) = b[1];
        *(uint4*)(base + 1*GMAT + r0g*GSTR + c0g*16) = b[2];
        *(uint4*)(base + 1*GMAT + r1g*GSTR + c1g*16) = b[3];
        *(uint4*)(base + 2*GMAT + r0g*GSTR + c0g*16) = b[4];
        *(uint4*)(base + 2*GMAT + r1g*GSTR + c1g*16) = b[5];
        *(uint4*)(base + 3*GMAT + r0g*GSTR + c0g*16) = b[6];
        *(uint4*)(base + 3*GMAT + r1g*GSTR + c1g*16) = b[7];
    };

    // ldmatrix row/col within tile (same formula for A and B: k-contiguous)
    const int lrow = lane & 15;           // row within 16-row frag group
    const int lcol = (lane >> 4) * 16;    // 0 or 16 bytes (k 0-7 / 8-15)

    uint4 pre[8];
    load_regs(0, pre);
    store_regs(0, pre);
    __syncthreads();

#pragma unroll 1
    for (int c = 0; c < 32; ++c) {
        const int s = c & 1;
        if (c < 31) load_regs((c + 1) * 32, pre);

        const uint32_t stA = sb + s * GSTAGE;
        const uint32_t stB = stA + 2 * GMAT;
#pragma unroll
        for (int ks = 0; ks < 2; ++ks) {
            uint32_t ah[2][4], al[2][4], bh[4][4], bl[4][4];
#pragma unroll
            for (int fm = 0; fm < 2; ++fm) {
                uint32_t ra = stA + (wm*32 + fm*16 + lrow)*GSTR + lcol + ks*32;
                ldmx4(ah[fm], ra);
                ldmx4(al[fm], ra + GMAT);
            }
#pragma unroll
            for (int g = 0; g < 4; ++g) {
                uint32_t rb = stB + (wn*64 + g*16 + lrow)*GSTR + lcol + ks*32;
                ldmx4(bh[g], rb);
                ldmx4(bl[g], rb + GMAT);
            }
#pragma unroll
            for (int fm = 0; fm < 2; ++fm)
#pragma unroll
                for (int fn = 0; fn < 8; ++fn) {
                    const int g = fn >> 1, sel = fn & 1;
                    float* cc = acc[fm*8 + fn];
                    mma_bf16(cc, ah[fm], bh[g][sel], bh[g][sel+2]);
                    mma_bf16(cc, ah[fm], bl[g][sel], bl[g][sel+2]);
                    mma_bf16(cc, al[fm], bh[g][sel], bh[g][sel+2]);
                }
        }
        if (c < 31) {
            __syncthreads();
            store_regs(s ^ 1, pre);
            __syncthreads();
        }
    }

    // epilogue
#pragma unroll
    for (int fm = 0; fm < 2; ++fm)
#pragma unroll
        for (int fn = 0; fn < 8; ++fn) {
            const float* cc = acc[fm*8 + fn];
            const int m = m0 + wm*32 + fm*16 + (lane >> 2);
            const int n = n0 + wn*64 + fn*8 + (lane & 3)*2;
            float2 bv = *(const float2*)&bias[n];
            float v0 = cc[0] + bv.x, v1 = cc[1] + bv.y;    // row m
            float v2 = cc[2] + bv.x, v3 = cc[3] + bv.y;    // row m+8
            if (MODE == 1) { v0 *= 0.125f; v1 *= 0.125f; v2 *= 0.125f; v3 *= 0.125f; }
            if (MODE == 0) {
                *(float2*)&Yf[(size_t)m * HD + n]       = make_float2(v0, v1);
                *(float2*)&Yf[(size_t)(m + 8) * HD + n] = make_float2(v2, v3);
            } else {
                const int b = m >> 10, sq = m & 1023;
                const int h = n >> 6,  d  = n & 63;
                size_t o0 = (((size_t)(b*HH + h))*HS + sq    )*HDK + d;
                size_t o1 = (((size_t)(b*HH + h))*HS + sq + 8)*HDK + d;
                if (MODE == 3) {
                    *(float2*)&Yf[o0] = make_float2(v0, v1);
                    *(float2*)&Yf[o1] = make_float2(v2, v3);
                } else {
                    uint32_t h0, l0, h1, l1;
                    split2(v0, v1, h0, l0);
                    split2(v2, v3, h1, l1);
                    *(uint32_t*)&Yhi[o0] = h0; *(uint32_t*)&Ylo[o0] = l0;
                    *(uint32_t*)&Yhi[o1] = h1; *(uint32_t*)&Ylo[o1] = l1;
                }
            }
        }
}

// ---------------------------------------------------------------------------
// Attention with MMA: CTA = (bh, 32 q rows). 256 threads (8 warps).
// Phase1 QK^T -> Ss (fp32 smem) ; Phase2 softmax + attn write ;
// Phase3 P@V -> ctx written split-bf16 into g_Xhi/g_Xlo [4096][1024].
// ---------------------------------------------------------------------------
#define SSTR 1032
#define OFF_SS 0
#define SS_BYTES (32*SSTR*4)            // 132096
#define OFF_R1 SS_BYTES                 // sQ (hi,lo) / sP (hi,lo)
#define QSTR 144
#define SQ_MAT (32*QSTR)                // 4608
#define PSTR 272
#define SP_MAT (32*PSTR)                // 8704
#define OFF_R2 (OFF_R1 + 17408)         // sK (hi,lo) / sVT (hi,lo)
#define KSTR 144
#define SK_MAT (128*KSTR)               // 18432
#define VSTR2 272
#define SVT_MAT (64*VSTR2)              // 17408
#define ATTN_SMEM (OFF_R2 + 2*SK_MAT)   // 186368

__global__ __launch_bounds__(256, 1)
void attn_mma(float* __restrict__ attn_out)
{
    extern __shared__ char sm[];
    const uint32_t sb = smem_u32(sm);
    float* Ss = (float*)sm;

    const int tid = threadIdx.x;
    const int wid = tid >> 5, lane = tid & 31;
    const int bh = blockIdx.y;
    const int q0 = blockIdx.x * 32;

    const __nv_bfloat16* Qhi = g_Qhi + (size_t)bh * HS * HDK;
    const __nv_bfloat16* Qlo = g_Qlo + (size_t)bh * HS * HDK;
    const __nv_bfloat16* Khi = g_Khi + (size_t)bh * HS * HDK;
    const __nv_bfloat16* Klo = g_Klo + (size_t)bh * HS * HDK;
    const __nv_bfloat16* VThi = g_VThi + (size_t)bh * HDK * HS;
    const __nv_bfloat16* VTlo = g_VTlo + (size_t)bh * HDK * HS;

    const int lrow = lane & 15;
    const int lcol = (lane >> 4) * 16;

    // ---- load Q tile (32 x 64) hi/lo: 1 granule per thread per matrix ----
    {
        int r = tid >> 3, cg = tid & 7;
        *(uint4*)(sm + OFF_R1 + r*QSTR + cg*16) =
            *((const uint4*)(Qhi + (size_t)(q0 + r)*HDK) + cg);
        *(uint4*)(sm + OFF_R1 + SQ_MAT + r*QSTR + cg*16) =
            *((const uint4*)(Qlo + (size_t)(q0 + r)*HDK) + cg);
    }

    // ---- Phase 1: scores ----
    const int wm = wid & 1, wn = wid >> 1;   // wm: 16 rows, wn: 32 keys
#pragma unroll 1
    for (int kt = 0; kt < 8; ++kt) {
        __syncthreads();
        // load K tile 128x64 hi/lo (4 granules per thread per matrix)
#pragma unroll
        for (int i = 0; i < 4; ++i) {
            int g = tid + i*256;
            int r = g >> 3, cg = g & 7;
            *(uint4*)(sm + OFF_R2 + r*KSTR + cg*16) =
                *((const uint4*)(Khi + (size_t)(kt*128 + r)*HDK) + cg);
            *(uint4*)(sm + OFF_R2 + SK_MAT + r*KSTR + cg*16) =
                *((const uint4*)(Klo + (size_t)(kt*128 + r)*HDK) + cg);
        }
        __syncthreads();

        float acc[4][4];
#pragma unroll
        for (int i = 0; i < 4; i++)
#pragma unroll
            for (int j = 0; j < 4; j++) acc[i][j] = 0.f;

#pragma unroll
        for (int ks = 0; ks < 4; ++ks) {
            uint32_t ah[4], al[4], bh[2][4], bl[2][4];
            uint32_t ra = sb + OFF_R1 + (wm*16 + lrow)*QSTR + lcol + ks*32;
            ldmx4(ah, ra);
            ldmx4(al, ra + SQ_MAT);
#pragma unroll
            for (int g = 0; g < 2; ++g) {
                uint32_t rb = sb + OFF_R2 + (wn*32 + g*16 + lrow)*KSTR + lcol + ks*32;
                ldmx4(bh[g], rb);
                ldmx4(bl[g], rb + SK_MAT);
            }
#pragma unroll
            for (int fn = 0; fn < 4; ++fn) {
                const int g = fn >> 1, sel = fn & 1;
                mma_bf16(acc[fn], ah, bh[g][sel], bh[g][sel+2]);
                mma_bf16(acc[fn], ah, bl[g][sel], bl[g][sel+2]);
                mma_bf16(acc[fn], al, bh[g][sel], bh[g][sel+2]);
            }
        }
        // store scores
#pragma unroll
        for (int fn = 0; fn < 4; ++fn) {
            int row = wm*16 + (lane >> 2);
            int col = kt*128 + wn*32 + fn*8 + (lane & 3)*2;
            *(float2*)&Ss[(size_t)row * SSTR + col]       = make_float2(acc[fn][0], acc[fn][1]);
            *(float2*)&Ss[(size_t)(row + 8) * SSTR + col] = make_float2(acc[fn][2], acc[fn][3]);
        }
    }
    __syncthreads();

    // ---- Phase 2: softmax (8 threads per row) ----
    {
        const int row = tid >> 3;
        const int t8  = tid & 7;
        float* srow = Ss + (size_t)row * SSTR;

        float mx = -1e30f;
#pragma unroll
        for (int i = 0; i < 32; i++) {
            float4 v = *(const float4*)&srow[t8*4 + i*32];
            mx = fmaxf(mx, fmaxf(fmaxf(v.x, v.y), fmaxf(v.z, v.w)));
        }
#pragma unroll
        for (int o = 4; o >= 1; o >>= 1)
            mx = fmaxf(mx, __shfl_xor_sync(0xffffffffu, mx, o));

        float sum = 0.f;
#pragma unroll
        for (int i = 0; i < 32; i++) {
            float4 v = *(float4*)&srow[t8*4 + i*32];
            v.x = __expf(v.x - mx); v.y = __expf(v.y - mx);
            v.z = __expf(v.z - mx); v.w = __expf(v.w - mx);
            sum += v.x + v.y + v.z + v.w;
            *(float4*)&srow[t8*4 + i*32] = v;
        }
#pragma unroll
        for (int o = 4; o >= 1; o >>= 1)
            sum += __shfl_xor_sync(0xffffffffu, sum, o);
        float inv = 1.f / sum;

        float* arow = attn_out + ((size_t)bh * HS + q0 + row) * HS;
#pragma unroll
        for (int i = 0; i < 32; i++) {
            float4 v = *(float4*)&srow[t8*4 + i*32];
            v.x *= inv; v.y *= inv; v.z *= inv; v.w *= inv;
            *(float4*)&srow[t8*4 + i*32] = v;
            *(float4*)&arow[t8*4 + i*32] = v;
        }
    }

    // ---- Phase 3: ctx = P @ V ----
    const int wn3 = wid >> 1;                  // d group: wn3*16
    float acc2[2][4];
#pragma unroll
    for (int i = 0; i < 2; i++)
#pragma unroll
        for (int j = 0; j < 4; j++) acc2[i][j] = 0.f;

#pragma unroll 1
    for (int kt = 0; kt < 8; ++kt) {
        __syncthreads();
        // convert P tile 32x128 -> bf16 hi/lo (8 pairs per thread)
#pragma unroll
        for (int i = 0; i < 8; ++i) {
            int p = tid + i*256;
            int row = p >> 6, cp = p & 63;
            float2 v = *(const float2*)&Ss[(size_t)row * SSTR + kt*128 + cp*2];
            uint32_t h, l;
            split2(v.x, v.y, h, l);
            *(uint32_t*)(sm + OFF_R1 + row*PSTR + cp*4) = h;
            *(uint32_t*)(sm + OFF_R1 + SP_MAT + row*PSTR + cp*4) = l;
        }
        // load VT tile 64 x 128keys hi/lo (4 granules per thread per matrix)
#pragma unroll
        for (int i = 0; i < 4; ++i) {
            int g = tid + i*256;
            int r = g >> 4, cg = g & 15;
            *(uint4*)(sm + OFF_R2 + r*VSTR2 + cg*16) =
                *((const uint4*)(VThi + (size_t)r*HS + kt*128) + cg);
            *(uint4*)(sm + OFF_R2 + SVT_MAT + r*VSTR2 + cg*16) =
                *((const uint4*)(VTlo + (size_t)r*HS + kt*128) + cg);
        }
        __syncthreads();

#pragma unroll
        for (int ks = 0; ks < 8; ++ks) {
            uint32_t ah[4], al[4], bh[4], bl[4];
            uint32_t ra = sb + OFF_R1 + (wm*16 + lrow)*PSTR + lcol + ks*32;
            ldmx4(ah, ra);
            ldmx4(al, ra + SP_MAT);
            uint32_t rb = sb + OFF_R2 + (wn3*16 + lrow)*VSTR2 + lcol + ks*32;
            ldmx4(bh, rb);
            ldmx4(bl, rb + SVT_MAT);
#pragma unroll
            for (int fn = 0; fn < 2; ++fn) {
                mma_bf16(acc2[fn], ah, bh[fn], bh[fn+2]);
                mma_bf16(acc2[fn], ah, bl[fn], bl[fn+2]);
                mma_bf16(acc2[fn], al, bh[fn], bh[fn+2]);
            }
        }
    }

    // epilogue: ctx -> g_Xhi/g_Xlo row-major [4096][1024]
    {
        const int b = bh >> 4, h = bh & 15;
#pragma unroll
        for (int fn = 0; fn < 2; ++fn) {
            int s  = q0 + wm*16 + (lane >> 2);
            int cl = h*64 + wn3*16 + fn*8 + (lane & 3)*2;
            size_t o0 = (size_t)(b*HS + s)     * HD + cl;
            size_t o1 = (size_t)(b*HS + s + 8) * HD + cl;
            uint32_t h0, l0, h1, l1;
            split2(acc2[fn][0], acc2[fn][1], h0, l0);
            split2(acc2[fn][2], acc2[fn][3], h1, l1);
            *(uint32_t*)&g_Xhi[o0] = h0; *(uint32_t*)&g_Xlo[o0] = l0;
            *(uint32_t*)&g_Xhi[o1] = h1; *(uint32_t*)&g_Xlo[o1] = l1;
        }
    }
}

// ---------------------------------------------------------------------------
extern "C" void kernel_launch(void* const* d_in, const int* in_sizes, int n_in,
                              void* d_out, int out_size)
{
    const float* q  = (const float*)d_in[0];
    const float* k  = (const float*)d_in[1];
    const float* v  = (const float*)d_in[2];
    const float* Wq = (const float*)d_in[3];
    const float* bq = (const float*)d_in[4];
    const float* Wk = (const float*)d_in[5];
    const float* bk = (const float*)d_in[6];
    const float* Wv = (const float*)d_in[7];
    const float* bv = (const float*)d_in[8];
    const float* Wo = (const float*)d_in[9];
    const float* bo = (const float*)d_in[10];

    float* out  = (float*)d_out;
    float* attn = out + OUT_ELEMS;

    __nv_bfloat16 *xhi, *xlo, *whi, *wlo, *qhi, *qlo, *khi, *klo;
    float* vf;
    cudaGetSymbolAddress((void**)&xhi, g_Xhi);
    cudaGetSymbolAddress((void**)&xlo, g_Xlo);
    cudaGetSymbolAddress((void**)&whi, g_Whi);
    cudaGetSymbolAddress((void**)&wlo, g_Wlo);
    cudaGetSymbolAddress((void**)&qhi, g_Qhi);
    cudaGetSymbolAddress((void**)&qlo, g_Qlo);
    cudaGetSymbolAddress((void**)&khi, g_Khi);
    cudaGetSymbolAddress((void**)&klo, g_Klo);
    cudaGetSymbolAddress((void**)&vf,  g_Vf);

    cudaFuncSetAttribute(gemm_mma<0>, cudaFuncAttributeMaxDynamicSharedMemorySize, GT_SMEM);
    cudaFuncSetAttribute(gemm_mma<1>, cudaFuncAttributeMaxDynamicSharedMemorySize, GT_SMEM);
    cudaFuncSetAttribute(gemm_mma<2>, cudaFuncAttributeMaxDynamicSharedMemorySize, GT_SMEM);
    cudaFuncSetAttribute(gemm_mma<3>, cudaFuncAttributeMaxDynamicSharedMemorySize, GT_SMEM);
    cudaFuncSetAttribute(attn_mma, cudaFuncAttributeMaxDynamicSharedMemorySize, ATTN_SMEM);

    const int n4 = OUT_ELEMS / 4;
    dim3 gsplit((n4 + 255) / 256);
    dim3 gwt(HD / 32, HD / 32), bwt(32, 8);
    dim3 ggemm(HD / 128, MTOT / 128);   // (8, 32)

    // Q projection
    split_k<<<gsplit, 256>>>((const float4*)q, (uint32_t*)xhi, (uint32_t*)xlo, n4);
    wT_split_k<<<gwt, bwt>>>(Wq, whi, wlo);
    gemm_mma<1><<<ggemm, 256, GT_SMEM>>>(xhi, xlo, bq, nullptr, qhi, qlo);
    // K projection
    split_k<<<gsplit, 256>>>((const float4*)k, (uint32_t*)xhi, (uint32_t*)xlo, n4);
    wT_split_k<<<gwt, bwt>>>(Wk, whi, wlo);
    gemm_mma<2><<<ggemm, 256, GT_SMEM>>>(xhi, xlo, bk, nullptr, khi, klo);
    // V projection
    split_k<<<gsplit, 256>>>((const float4*)v, (uint32_t*)xhi, (uint32_t*)xlo, n4);
    wT_split_k<<<gwt, bwt>>>(Wv, whi, wlo);
    gemm_mma<3><<<ggemm, 256, GT_SMEM>>>(xhi, xlo, bv, vf, nullptr, nullptr);
    vT_split_k<<<dim3(64, NBH), bwt>>>();

    // attention (writes attn + ctx split into g_Xhi/g_Xlo)
    attn_mma<<<dim3(HS / 32, NBH), 256, ATTN_SMEM>>>(attn);

    // output projection
    wT_split_k<<<gwt, bwt>>>(Wo, whi, wlo);
    gemm_mma<0><<<ggemm, 256, GT_SMEM>>>(xhi, xlo, bo, out, nullptr, nullptr);
}

// round 4
// speedup vs baseline: 2.2814x; 1.0752x over previous
#include <cuda_runtime.h>
#include <cuda_bf16.h>
#include <cstdint>

// Problem constants
#define HB   4
#define HS   1024
#define HD   1024
#define HH   16
#define HDK  64
#define MTOT (HB*HS)          // 4096
#define NBH  (HB*HH)          // 64
#define OUT_ELEMS (MTOT*HD)   // 4194304

// Scratch (allocation-free device globals)
__device__ __nv_bfloat16 g_Xhi[3*MTOT*HD];   // split inputs q,k,v; slot0 reused for ctx
__device__ __nv_bfloat16 g_Xlo[3*MTOT*HD];
__device__ __nv_bfloat16 g_Whi[4*HD*HD];     // W^T [n][k] for Wq,Wk,Wv,Wo
__device__ __nv_bfloat16 g_Wlo[4*HD*HD];
__device__ __nv_bfloat16 g_Qhi[NBH*HS*HDK];  // [bh][s][d] pre-scaled
__device__ __nv_bfloat16 g_Qlo[NBH*HS*HDK];
__device__ __nv_bfloat16 g_Khi[NBH*HS*HDK];
__device__ __nv_bfloat16 g_Klo[NBH*HS*HDK];
__device__ float         g_Vf [NBH*HS*HDK];  // [bh][s][d] fp32
__device__ __nv_bfloat16 g_VThi[NBH*HDK*HS]; // [bh][d][s]
__device__ __nv_bfloat16 g_VTlo[NBH*HDK*HS];

// ---------------------------------------------------------------------------
// helpers
// ---------------------------------------------------------------------------
__device__ __forceinline__ uint32_t smem_u32(const void* p) {
    uint32_t a;
    asm("{ .reg .u64 t; cvta.to.shared.u64 t, %1; cvt.u32.u64 %0, t; }"
        : "=r"(a) : "l"(p));
    return a;
}
__device__ __forceinline__ void ldmx4(uint32_t* r, uint32_t addr) {
    asm volatile("ldmatrix.sync.aligned.m8n8.x4.shared.b16 {%0,%1,%2,%3}, [%4];"
        : "=r"(r[0]), "=r"(r[1]), "=r"(r[2]), "=r"(r[3]) : "r"(addr));
}
__device__ __forceinline__ void mma_bf16(float* c, const uint32_t* a,
                                         uint32_t b0, uint32_t b1) {
    asm volatile(
        "mma.sync.aligned.m16n8k16.row.col.f32.bf16.bf16.f32 "
        "{%0,%1,%2,%3}, {%4,%5,%6,%7}, {%8,%9}, {%0,%1,%2,%3};"
        : "+f"(c[0]), "+f"(c[1]), "+f"(c[2]), "+f"(c[3])
        : "r"(a[0]), "r"(a[1]), "r"(a[2]), "r"(a[3]), "r"(b0), "r"(b1));
}
__device__ __forceinline__ void split2(float x, float y,
                                       uint32_t& hi, uint32_t& lo) {
    __nv_bfloat16 hx = __float2bfloat16(x), hy = __float2bfloat16(y);
    __nv_bfloat16 lx = __float2bfloat16(x - __bfloat162float(hx));
    __nv_bfloat16 ly = __float2bfloat16(y - __bfloat162float(hy));
    __nv_bfloat162 h2(hx, hy), l2(lx, ly);
    hi = *(uint32_t*)&h2;
    lo = *(uint32_t*)&l2;
}
#define CP16(dst, src) asm volatile("cp.async.cg.shared.global [%0], [%1], 16;" :: "r"(dst), "l"(src))
#define CP_COMMIT()    asm volatile("cp.async.commit_group;" ::: "memory")
#define CP_WAIT1()     asm volatile("cp.async.wait_group 1;" ::: "memory")
#define CP_WAIT0()     asm volatile("cp.async.wait_group 0;" ::: "memory")

// ---------------------------------------------------------------------------
// q,k,v fp32 -> (hi, lo) bf16 split, one launch
// ---------------------------------------------------------------------------
#define N4 (OUT_ELEMS/4)
__global__ __launch_bounds__(256)
void splitQKV_k(const float4* __restrict__ q, const float4* __restrict__ k,
                const float4* __restrict__ v)
{
    int i = blockIdx.x * 256 + threadIdx.x;          // 0 .. 3*N4
    int z = i / N4, j = i - z * N4;
    const float4* src = (z == 0) ? q : (z == 1) ? k : v;
    float4 val = src[j];
    uint32_t* hi = (uint32_t*)(g_Xhi + (size_t)z * OUT_ELEMS);
    uint32_t* lo = (uint32_t*)(g_Xlo + (size_t)z * OUT_ELEMS);
    uint32_t h0, l0, h1, l1;
    split2(val.x, val.y, h0, l0);
    split2(val.z, val.w, h1, l1);
    hi[2*j] = h0; hi[2*j+1] = h1;
    lo[2*j] = l0; lo[2*j+1] = l1;
}

// ---------------------------------------------------------------------------
// All 4 weights: W[k][n] fp32 -> W^T hi/lo [n][k] bf16, one launch
// ---------------------------------------------------------------------------
__global__ __launch_bounds__(256)
void wT4_k(const float* __restrict__ Wq, const float* __restrict__ Wk,
           const float* __restrict__ Wv, const float* __restrict__ Wo)
{
    __shared__ float t[32][33];
    const int z = blockIdx.z;
    const float* W = (z == 0) ? Wq : (z == 1) ? Wk : (z == 2) ? Wv : Wo;
    __nv_bfloat16* hiT = g_Whi + (size_t)z * HD * HD;
    __nv_bfloat16* loT = g_Wlo + (size_t)z * HD * HD;
    int k0 = blockIdx.y * 32, n0 = blockIdx.x * 32;
    int tx = threadIdx.x, ty = threadIdx.y;   // (32, 8)
#pragma unroll
    for (int j = 0; j < 32; j += 8)
        t[ty + j][tx] = W[(size_t)(k0 + ty + j) * HD + n0 + tx];
    __syncthreads();
#pragma unroll
    for (int j = 0; j < 32; j += 8) {
        float v = t[tx][ty + j];
        __nv_bfloat16 h = __float2bfloat16(v);
        __nv_bfloat16 l = __float2bfloat16(v - __bfloat162float(h));
        size_t o = (size_t)(n0 + ty + j) * HD + k0 + tx;
        hiT[o] = h;
        loT[o] = l;
    }
}

// ---------------------------------------------------------------------------
// g_Vf [bh][s][d] -> g_VThi/lo [bh][d][s]
// ---------------------------------------------------------------------------
__global__ __launch_bounds__(256)
void vT_split_k()
{
    __shared__ float t[32][33];
    int bh = blockIdx.y;
    int s0 = (blockIdx.x & 31) * 32;
    int d0 = (blockIdx.x >> 5) * 32;
    int tx = threadIdx.x, ty = threadIdx.y;   // (32, 8)
    const float* V = g_Vf + (size_t)bh * HS * HDK;
#pragma unroll
    for (int j = 0; j < 32; j += 8)
        t[ty + j][tx] = V[(size_t)(s0 + ty + j) * HDK + d0 + tx];
    __syncthreads();
    __nv_bfloat16* Hi = g_VThi + (size_t)bh * HDK * HS;
    __nv_bfloat16* Lo = g_VTlo + (size_t)bh * HDK * HS;
#pragma unroll
    for (int j = 0; j < 32; j += 8) {
        float v = t[tx][ty + j];
        __nv_bfloat16 h = __float2bfloat16(v);
        __nv_bfloat16 l = __float2bfloat16(v - __bfloat162float(h));
        size_t o = (size_t)(d0 + ty + j) * HS + s0 + tx;
        Hi[o] = h;
        Lo[o] = l;
    }
}

// ---------------------------------------------------------------------------
// Dense GEMM (BM=128,BN=128,BK=32), cp.async 3-stage, split-bf16 (3 MMAs).
// PROJ=true: blockIdx.z in {0,1,2} = Q/K/V with fused epilogues.
// PROJ=false: out = ctx @ Wo + bo, fp32 row-major.
// ---------------------------------------------------------------------------
#define GSTR 80                     // 64B data + 16 pad
#define GMAT (128*GSTR)             // 10240
#define GSTAGE (4*GMAT)             // 40960 (Ahi,Alo,Bhi,Blo)
#define GT_SMEM (3*GSTAGE)          // 122880

template<bool PROJ>
__global__ __launch_bounds__(256, 1)
void gemm5(const float* __restrict__ b0, const float* __restrict__ b1,
           const float* __restrict__ b2, float* __restrict__ outp)
{
    extern __shared__ char sm[];
    const uint32_t sb = smem_u32(sm);
    const int z = PROJ ? blockIdx.z : 3;
    const int tid = threadIdx.x;
    const int wid = tid >> 5, lane = tid & 31;
    const int wm = wid & 3, wn = wid >> 2;
    const int m0 = blockIdx.y * 128, n0 = blockIdx.x * 128;

    const __nv_bfloat16* Xhi = g_Xhi + (PROJ ? (size_t)z * OUT_ELEMS : 0);
    const __nv_bfloat16* Xlo = g_Xlo + (PROJ ? (size_t)z * OUT_ELEMS : 0);
    const __nv_bfloat16* Whi = g_Whi + (size_t)z * HD * HD;
    const __nv_bfloat16* Wlo = g_Wlo + (size_t)z * HD * HD;
    const float* bias = PROJ ? ((z == 0) ? b0 : (z == 1) ? b1 : b2) : b0;

    float acc[16][4];
#pragma unroll
    for (int i = 0; i < 16; i++)
#pragma unroll
        for (int j = 0; j < 4; j++) acc[i][j] = 0.f;

    const int r0 = tid >> 2, c0 = tid & 3;    // 2 granules/thread/matrix
    const int r1 = r0 + 64;

    auto cp_stage = [&](int st, int k0) {
        uint32_t d = sb + st * GSTAGE;
        CP16(d + 0*GMAT + r0*GSTR + c0*16, Xhi + (size_t)(m0 + r0)*HD + k0 + c0*8);
        CP16(d + 0*GMAT + r1*GSTR + c0*16, Xhi + (size_t)(m0 + r1)*HD + k0 + c0*8);
        CP16(d + 1*GMAT + r0*GSTR + c0*16, Xlo + (size_t)(m0 + r0)*HD + k0 + c0*8);
        CP16(d + 1*GMAT + r1*GSTR + c0*16, Xlo + (size_t)(m0 + r1)*HD + k0 + c0*8);
        CP16(d + 2*GMAT + r0*GSTR + c0*16, Whi + (size_t)(n0 + r0)*HD + k0 + c0*8);
        CP16(d + 2*GMAT + r1*GSTR + c0*16, Whi + (size_t)(n0 + r1)*HD + k0 + c0*8);
        CP16(d + 3*GMAT + r0*GSTR + c0*16, Wlo + (size_t)(n0 + r0)*HD + k0 + c0*8);
        CP16(d + 3*GMAT + r1*GSTR + c0*16, Wlo + (size_t)(n0 + r1)*HD + k0 + c0*8);
        CP_COMMIT();
    };

    const int lrow = lane & 15;
    const int lcol = (lane >> 4) * 16;

    cp_stage(0, 0);
    cp_stage(1, 32);

    int s = 0;
#pragma unroll 1
    for (int c = 0; c < 32; ++c) {
        if (c < 31) { CP_WAIT1(); } else { CP_WAIT0(); }
        __syncthreads();

        const uint32_t stA = sb + s * GSTAGE;
        const uint32_t stB = stA + 2 * GMAT;
#pragma unroll
        for (int ks = 0; ks < 2; ++ks) {
            uint32_t ah[2][4], al[2][4], bh[4][4], bl[4][4];
#pragma unroll
            for (int fm = 0; fm < 2; ++fm) {
                uint32_t ra = stA + (wm*32 + fm*16 + lrow)*GSTR + lcol + ks*32;
                ldmx4(ah[fm], ra);
                ldmx4(al[fm], ra + GMAT);
            }
#pragma unroll
            for (int g = 0; g < 4; ++g) {
                uint32_t rb = stB + (wn*64 + g*16 + lrow)*GSTR + lcol + ks*32;
                ldmx4(bh[g], rb);
                ldmx4(bl[g], rb + GMAT);
            }
#pragma unroll
            for (int fm = 0; fm < 2; ++fm)
#pragma unroll
                for (int fn = 0; fn < 8; ++fn) {
                    const int g = fn >> 1, sel = fn & 1;
                    float* cc = acc[fm*8 + fn];
                    mma_bf16(cc, ah[fm], bh[g][sel], bh[g][sel+2]);
                    mma_bf16(cc, ah[fm], bl[g][sel], bl[g][sel+2]);
                    mma_bf16(cc, al[fm], bh[g][sel], bh[g][sel+2]);
                }
        }
        __syncthreads();
        if (c + 2 < 32) cp_stage((s + 2) % 3, (c + 2) * 32);
        s = (s + 1) % 3;
    }

    // epilogue
#pragma unroll
    for (int fm = 0; fm < 2; ++fm)
#pragma unroll
        for (int fn = 0; fn < 8; ++fn) {
            const float* cc = acc[fm*8 + fn];
            const int m = m0 + wm*32 + fm*16 + (lane >> 2);
            const int n = n0 + wn*64 + fn*8 + (lane & 3)*2;
            float2 bv = *(const float2*)&bias[n];
            float v0 = cc[0] + bv.x, v1 = cc[1] + bv.y;    // row m
            float v2 = cc[2] + bv.x, v3 = cc[3] + bv.y;    // row m+8
            if (!PROJ) {
                *(float2*)&outp[(size_t)m * HD + n]       = make_float2(v0, v1);
                *(float2*)&outp[(size_t)(m + 8) * HD + n] = make_float2(v2, v3);
            } else {
                const int b = m >> 10, sq = m & 1023;
                const int h = n >> 6,  d  = n & 63;
                size_t o0 = (((size_t)(b*HH + h))*HS + sq    )*HDK + d;
                size_t o1 = (((size_t)(b*HH + h))*HS + sq + 8)*HDK + d;
                if (z == 2) {
                    *(float2*)&g_Vf[o0] = make_float2(v0, v1);
                    *(float2*)&g_Vf[o1] = make_float2(v2, v3);
                } else {
                    if (z == 0) { v0 *= 0.125f; v1 *= 0.125f; v2 *= 0.125f; v3 *= 0.125f; }
                    uint32_t h0, l0, h1, l1;
                    split2(v0, v1, h0, l0);
                    split2(v2, v3, h1, l1);
                    __nv_bfloat16* Yhi = (z == 0) ? g_Qhi : g_Khi;
                    __nv_bfloat16* Ylo = (z == 0) ? g_Qlo : g_Klo;
                    *(uint32_t*)&Yhi[o0] = h0; *(uint32_t*)&Ylo[o0] = l0;
                    *(uint32_t*)&Yhi[o1] = h1; *(uint32_t*)&Ylo[o1] = l1;
                }
            }
        }
}

// ---------------------------------------------------------------------------
// Attention QK^T + softmax. CTA = (32 q rows, bh). cp.async 2-stage K tiles.
// Writes attn probabilities to gmem.
// ---------------------------------------------------------------------------
#define SSTR 1032
#define SS_BYTES (32*SSTR*4)            // 132096
#define OFF_Q SS_BYTES
#define QSTR 144
#define SQ_MAT (32*QSTR)                // 4608
#define OFF_K (OFF_Q + 2*SQ_MAT)        // 141312
#define KSTR 144
#define SK_MAT (128*KSTR)               // 18432
#define KSTG (2*SK_MAT)                 // 36864 per stage
#define ATTN_SMEM (OFF_K + 2*KSTG)      // 215040

__global__ __launch_bounds__(256, 1)
void attn_qk(float* __restrict__ attn_out)
{
    extern __shared__ char sm[];
    const uint32_t sb = smem_u32(sm);
    float* Ss = (float*)sm;

    const int tid = threadIdx.x;
    const int wid = tid >> 5, lane = tid & 31;
    const int bh = blockIdx.y;
    const int q0 = blockIdx.x * 32;

    const __nv_bfloat16* Qhi = g_Qhi + (size_t)bh * HS * HDK;
    const __nv_bfloat16* Qlo = g_Qlo + (size_t)bh * HS * HDK;
    const __nv_bfloat16* Khi = g_Khi + (size_t)bh * HS * HDK;
    const __nv_bfloat16* Klo = g_Klo + (size_t)bh * HS * HDK;

    const int lrow = lane & 15;
    const int lcol = (lane >> 4) * 16;

    // Q tile 32x64 hi/lo: 512 granules, 2/thread
    {
#pragma unroll
        for (int i = 0; i < 2; ++i) {
            int g = tid + i * 256;
            int mat = g >> 8, gg = g & 255;
            int r = gg >> 3, cg = gg & 7;
            const __nv_bfloat16* src = (mat ? Qlo : Qhi) + (size_t)(q0 + r)*HDK + cg*8;
            *(uint4*)(sm + OFF_Q + mat*SQ_MAT + r*QSTR + cg*16) = *(const uint4*)src;
        }
    }

    auto cp_K = [&](int st, int kt) {
        uint32_t d = sb + OFF_K + st * KSTG;
#pragma unroll
        for (int i = 0; i < 8; ++i) {
            int g = tid + i * 256;
            int mat = g >> 10, gg = g & 1023;
            int r = gg >> 3, cg = gg & 7;
            const __nv_bfloat16* src = (mat ? Klo : Khi) + (size_t)(kt*128 + r)*HDK + cg*8;
            CP16(d + mat*SK_MAT + r*KSTR + cg*16, src);
        }
        CP_COMMIT();
    };

    cp_K(0, 0);

    const int wm = wid & 1, wn = wid >> 1;   // wm: 16 q rows, wn: 32 keys
#pragma unroll 1
    for (int kt = 0; kt < 8; ++kt) {
        const int s = kt & 1;
        if (kt < 7) cp_K(s ^ 1, kt + 1);
        if (kt < 7) { CP_WAIT1(); } else { CP_WAIT0(); }
        __syncthreads();

        float acc[4][4];
#pragma unroll
        for (int i = 0; i < 4; i++)
#pragma unroll
            for (int j = 0; j < 4; j++) acc[i][j] = 0.f;

        const uint32_t stK = sb + OFF_K + s * KSTG;
#pragma unroll
        for (int ks = 0; ks < 4; ++ks) {
            uint32_t ah[4], al[4], bh[2][4], bl[2][4];
            uint32_t ra = sb + OFF_Q + (wm*16 + lrow)*QSTR + lcol + ks*32;
            ldmx4(ah, ra);
            ldmx4(al, ra + SQ_MAT);
#pragma unroll
            for (int g = 0; g < 2; ++g) {
                uint32_t rb = stK + (wn*32 + g*16 + lrow)*KSTR + lcol + ks*32;
                ldmx4(bh[g], rb);
                ldmx4(bl[g], rb + SK_MAT);
            }
#pragma unroll
            for (int fn = 0; fn < 4; ++fn) {
                const int g = fn >> 1, sel = fn & 1;
                mma_bf16(acc[fn], ah, bh[g][sel], bh[g][sel+2]);
                mma_bf16(acc[fn], ah, bl[g][sel], bl[g][sel+2]);
                mma_bf16(acc[fn], al, bh[g][sel], bh[g][sel+2]);
            }
        }
#pragma unroll
        for (int fn = 0; fn < 4; ++fn) {
            int row = wm*16 + (lane >> 2);
            int col = kt*128 + wn*32 + fn*8 + (lane & 3)*2;
            *(float2*)&Ss[(size_t)row * SSTR + col]       = make_float2(acc[fn][0], acc[fn][1]);
            *(float2*)&Ss[(size_t)(row + 8) * SSTR + col] = make_float2(acc[fn][2], acc[fn][3]);
        }
        __syncthreads();
    }

    // softmax: 8 threads/row, write attn
    {
        const int row = tid >> 3;
        const int t8  = tid & 7;
        float* srow = Ss + (size_t)row * SSTR;

        float mx = -1e30f;
#pragma unroll
        for (int i = 0; i < 32; i++) {
            float4 v = *(const float4*)&srow[t8*4 + i*32];
            mx = fmaxf(mx, fmaxf(fmaxf(v.x, v.y), fmaxf(v.z, v.w)));
        }
#pragma unroll
        for (int o = 4; o >= 1; o >>= 1)
            mx = fmaxf(mx, __shfl_xor_sync(0xffffffffu, mx, o));

        float sum = 0.f;
#pragma unroll
        for (int i = 0; i < 32; i++) {
            float4 v = *(float4*)&srow[t8*4 + i*32];
            v.x = __expf(v.x - mx); v.y = __expf(v.y - mx);
            v.z = __expf(v.z - mx); v.w = __expf(v.w - mx);
            sum += v.x + v.y + v.z + v.w;
            *(float4*)&srow[t8*4 + i*32] = v;
        }
#pragma unroll
        for (int o = 4; o >= 1; o >>= 1)
            sum += __shfl_xor_sync(0xffffffffu, sum, o);
        float inv = 1.f / sum;

        float* arow = attn_out + ((size_t)bh * HS + q0 + row) * HS;
#pragma unroll
        for (int i = 0; i < 32; i++) {
            float4 v = *(float4*)&srow[t8*4 + i*32];
            v.x *= inv; v.y *= inv; v.z *= inv; v.w *= inv;
            *(float4*)&arow[t8*4 + i*32] = v;
        }
    }
}

// ---------------------------------------------------------------------------
// PV batched GEMM: ctx[bh][128 s][64 d] = P[s][k] @ V[k][d], k=1024, BK=64.
// P read fp32 from attn, split on the fly; VT hi/lo via cp.async. 2-stage.
// ctx written split-bf16 into g_Xhi/g_Xlo slot 0, row-major [4096][1024].
// ---------------------------------------------------------------------------
#define ASTR 144
#define A_MAT (128*ASTR)                // 18432
#define B_MAT (64*ASTR)                 // 9216
#define POFF_B (2*A_MAT)                // 36864
#define PSTAGE (POFF_B + 2*B_MAT)       // 55296
#define PV_SMEM (2*PSTAGE)              // 110592

__global__ __launch_bounds__(256, 1)
void pv_mma(const float* __restrict__ attn)
{
    extern __shared__ char sm[];
    const uint32_t sb = smem_u32(sm);
    const int tid = threadIdx.x;
    const int wid = tid >> 5, lane = tid & 31;
    const int wm = wid & 3, wn = wid >> 2;   // wm: 32 rows, wn: 32 d cols
    const int m0 = blockIdx.x * 128;
    const int bh = blockIdx.y;

    const float* P = attn + (size_t)bh * HS * HS;
    const __nv_bfloat16* VThi = g_VThi + (size_t)bh * HDK * HS;
    const __nv_bfloat16* VTlo = g_VTlo + (size_t)bh * HDK * HS;

    const int lrow = lane & 15;
    const int lcol = (lane >> 4) * 16;

    // A granule mapping: 2048 fp32-f4 granules (128 rows x 16), 8/thread
    const int ar = tid >> 1;                 // handled via loop below
    (void)ar;

    float4 areg[8];
    auto loadA = [&](int k0) {
#pragma unroll
        for (int i = 0; i < 8; ++i) {
            int g = tid + i * 256;
            int r = g >> 4, cg = g & 15;
            areg[i] = *(const float4*)(P + (size_t)(m0 + r)*HS + k0 + cg*4);
        }
    };
    auto storeA = [&](int st) {
        uint32_t d = sb + st * PSTAGE;
#pragma unroll
        for (int i = 0; i < 8; ++i) {
            int g = tid + i * 256;
            int r = g >> 4, cg = g & 15;
            uint32_t h0, l0, h1, l1;
            split2(areg[i].x, areg[i].y, h0, l0);
            split2(areg[i].z, areg[i].w, h1, l1);
            uint32_t off = r*ASTR + cg*8;
            *(uint2*)(sm + (d - sb) + off)         = make_uint2(h0, h1);
            *(uint2*)(sm + (d - sb) + A_MAT + off) = make_uint2(l0, l1);
        }
    };
    auto cp_B = [&](int st, int k0) {
        uint32_t d = sb + st * PSTAGE + POFF_B;
#pragma unroll
        for (int i = 0; i < 4; ++i) {
            int g = tid + i * 256;
            int mat = g >> 9, gg = g & 511;
            int r = gg >> 3, cg = gg & 7;
            const __nv_bfloat16* src = (mat ? VTlo : VThi) + (size_t)r*HS + k0 + cg*8;
            CP16(d + mat*B_MAT + r*ASTR + cg*16, src);
        }
        CP_COMMIT();
    };

    float acc[8][4];
#pragma unroll
    for (int i = 0; i < 8; i++)
#pragma unroll
        for (int j = 0; j < 4; j++) acc[i][j] = 0.f;

    loadA(0);
    cp_B(0, 0);

#pragma unroll 1
    for (int c = 0; c < 16; ++c) {
        const int s = c & 1;
        storeA(s);
        if (c < 15) cp_B(s ^ 1, (c + 1) * 64);
        if (c < 15) { CP_WAIT1(); } else { CP_WAIT0(); }
        __syncthreads();
        if (c < 15) loadA((c + 1) * 64);

        const uint32_t stA = sb + s * PSTAGE;
        const uint32_t stB = stA + POFF_B;
#pragma unroll
        for (int ks = 0; ks < 4; ++ks) {
            uint32_t ah[2][4], al[2][4], bhf[2][4], blf[2][4];
#pragma unroll
            for (int fm = 0; fm < 2; ++fm) {
                uint32_t ra = stA + (wm*32 + fm*16 + lrow)*ASTR + lcol + ks*32;
                ldmx4(ah[fm], ra);
                ldmx4(al[fm], ra + A_MAT);
            }
#pragma unroll
            for (int g = 0; g < 2; ++g) {
                uint32_t rb = stB + (wn*32 + g*16 + lrow)*ASTR + lcol + ks*32;
                ldmx4(bhf[g], rb);
                ldmx4(blf[g], rb + B_MAT);
            }
#pragma unroll
            for (int fm = 0; fm < 2; ++fm)
#pragma unroll
                for (int fn = 0; fn < 4; ++fn) {
                    const int g = fn >> 1, sel = fn & 1;
                    float* cc = acc[fm*4 + fn];
                    mma_bf16(cc, ah[fm], bhf[g][sel], bhf[g][sel+2]);
                    mma_bf16(cc, ah[fm], blf[g][sel], blf[g][sel+2]);
                    mma_bf16(cc, al[fm], bhf[g][sel], bhf[g][sel+2]);
                }
        }
        __syncthreads();
    }

    // epilogue: ctx split -> g_Xhi/g_Xlo slot0 row-major [4096][1024]
    const int b = bh >> 4, h = bh & 15;
#pragma unroll
    for (int fm = 0; fm < 2; ++fm)
#pragma unroll
        for (int fn = 0; fn < 4; ++fn) {
            const float* cc = acc[fm*4 + fn];
            int sq = m0 + wm*32 + fm*16 + (lane >> 2);
            int d  = wn*32 + fn*8 + (lane & 3)*2;
            size_t o0 = (size_t)(b*HS + sq)     * HD + h*64 + d;
            size_t o1 = (size_t)(b*HS + sq + 8) * HD + h*64 + d;
            uint32_t h0, l0, h1, l1;
            split2(cc[0], cc[1], h0, l0);
            split2(cc[2], cc[3], h1, l1);
            *(uint32_t*)&g_Xhi[o0] = h0; *(uint32_t*)&g_Xlo[o0] = l0;
            *(uint32_t*)&g_Xhi[o1] = h1; *(uint32_t*)&g_Xlo[o1] = l1;
        }
}

// ---------------------------------------------------------------------------
extern "C" void kernel_launch(void* const* d_in, const int* in_sizes, int n_in,
                              void* d_out, int out_size)
{
    const float* q  = (const float*)d_in[0];
    const float* k  = (const float*)d_in[1];
    const float* v  = (const float*)d_in[2];
    const float* Wq = (const float*)d_in[3];
    const float* bq = (const float*)d_in[4];
    const float* Wk = (const float*)d_in[5];
    const float* bk = (const float*)d_in[6];
    const float* Wv = (const float*)d_in[7];
    const float* bv = (const float*)d_in[8];
    const float* Wo = (const float*)d_in[9];
    const float* bo = (const float*)d_in[10];

    float* out  = (float*)d_out;
    float* attn = out + OUT_ELEMS;

    cudaFuncSetAttribute(gemm5<true>,  cudaFuncAttributeMaxDynamicSharedMemorySize, GT_SMEM);
    cudaFuncSetAttribute(gemm5<false>, cudaFuncAttributeMaxDynamicSharedMemorySize, GT_SMEM);
    cudaFuncSetAttribute(attn_qk, cudaFuncAttributeMaxDynamicSharedMemorySize, ATTN_SMEM);
    cudaFuncSetAttribute(pv_mma, cudaFuncAttributeMaxDynamicSharedMemorySize, PV_SMEM);

    // 1. split q,k,v -> bf16 hi/lo
    splitQKV_k<<<3 * N4 / 256, 256>>>((const float4*)q, (const float4*)k,
                                      (const float4*)v);
    // 2. transpose+split all 4 weights
    wT4_k<<<dim3(HD/32, HD/32, 4), dim3(32, 8)>>>(Wq, Wk, Wv, Wo);
    // 3. Q,K,V projections in one launch
    gemm5<true><<<dim3(HD/128, MTOT/128, 3), 256, GT_SMEM>>>(bq, bk, bv, nullptr);
    // 4. V -> V^T split
    vT_split_k<<<dim3(64, NBH), dim3(32, 8)>>>();
    // 5. QK^T + softmax -> attn
    attn_qk<<<dim3(HS/32, NBH), 256, ATTN_SMEM>>>(attn);
    // 6. ctx = P @ V (reads attn) -> split into g_Xhi/g_Xlo slot0
    pv_mma<<<dim3(HS/128, NBH), 256, PV_SMEM>>>(attn);
    // 7. out = ctx @ Wo + bo
    gemm5<false><<<dim3(HD/128, MTOT/128), 256, GT_SMEM>>>(bo, nullptr, nullptr, out);
}